// round 2
// baseline (speedup 1.0000x reference)
#include <cuda_runtime.h>
#include <math.h>

// ModulatedConv2D: B=16, Cin=Cout=512, H=W=32, k=3, SAME.
// y[b,o,h,w] = G*sigma[b,o] * sum_{i,t} weight[o,i,t] * style[b,i] * x[b,i,h+dh,w+dw]
// sigma[b,o] = rsqrt(G^2 * sum_i style[b,i]^2 * wsq[o,i] + eps)

#define BATCH 16
#define CH    512
#define HW    32
#define KK    9
#define EPSV  1e-8f

// scratch (static device globals, allowed)
__device__ float g_wsqT[CH * CH];     // [i][o] transposed sum-of-squares of weight taps
__device__ float g_scale[BATCH * CH]; // G * sigma[b][o]

// ---------------------------------------------------------------------------
// Kernel 1: wsq[o,i] = sum_t weight[o,i,t]^2, stored transposed as wsqT[i*512+o]
// ---------------------------------------------------------------------------
__global__ void wsq_kernel(const float* __restrict__ w) {
    int t = blockIdx.x * blockDim.x + threadIdx.x;
    if (t >= CH * CH) return;
    int o = t >> 9;
    int i = t & 511;
    const float* p = w + (size_t)t * KK;  // (o*512+i)*9
    float s = 0.f;
#pragma unroll
    for (int k = 0; k < KK; k++) s += p[k] * p[k];
    g_wsqT[i * CH + o] = s;
}

// ---------------------------------------------------------------------------
// Kernel 2: per-(b,o) scale = G * rsqrt(G^2 * sum_i style[b,i]^2 * wsq[o,i] + eps)
// One block per batch sample, 512 threads (one per o). wsqT reads coalesced.
// ---------------------------------------------------------------------------
__global__ void scale_kernel(const float* __restrict__ style) {
    const float GAIN = rsqrtf((float)(CH * KK)); // 1/sqrt(4608)
    int b = blockIdx.x;
    int o = threadIdx.x;
    __shared__ float s2[CH];
    float sv = style[b * CH + o];
    s2[o] = sv * sv;
    __syncthreads();
    float acc = 0.f;
#pragma unroll 4
    for (int i = 0; i < CH; i++) acc += s2[i] * g_wsqT[i * CH + o];
    g_scale[b * CH + o] = GAIN * rsqrtf(acc * GAIN * GAIN + EPSV);
}

// ---------------------------------------------------------------------------
// Kernel 3: main conv. Block tile: 64 out-channels x (8 rows x 32 cols).
// 256 threads; each thread: 8 oc x 8 rows at one column (tx). IC chunk = 8.
// style folded into the x smem tile at load time.
// ---------------------------------------------------------------------------
#define OC_TILE 64
#define RTILE   8
#define ICC     8
#define XW      34            // 32 cols + 2 halo
#define XROWS   (RTILE + 2)   // 10
#define WSTRIDE 65            // padded [j][oc] stride (conflict-free stores)

__global__ __launch_bounds__(256, 2)
void conv_kernel(const float* __restrict__ x,
                 const float* __restrict__ style,
                 const float* __restrict__ w,
                 float* __restrict__ out) {
    __shared__ float xs[ICC][XROWS * XW];        // 8 * 340 floats
    __shared__ float ws[ICC * KK * WSTRIDE];     // 72 * 65 floats

    const int tid = threadIdx.x;
    const int tx  = tid & 31;   // column 0..31
    const int ty  = tid >> 5;   // oc-group 0..7
    const int b   = blockIdx.z;
    const int oc0 = blockIdx.y * OC_TILE;
    const int r0  = blockIdx.x * RTILE;

    const float* xb = x + (size_t)b * CH * HW * HW;
    const float* sb = style + b * CH;

    float acc[8][8];
#pragma unroll
    for (int o = 0; o < 8; o++)
#pragma unroll
        for (int r = 0; r < 8; r++) acc[o][r] = 0.f;

    for (int ic0 = 0; ic0 < CH; ic0 += ICC) {
        __syncthreads();  // previous chunk's compute done before overwrite

        // ---- load x tile (with style folded in), zero-padded halo ----
        // 8 ic * 10 rows * 34 cols = 2720 elements
        for (int idx = tid; idx < ICC * XROWS * XW; idx += 256) {
            int ic  = idx / (XROWS * XW);
            int rem = idx - ic * (XROWS * XW);
            int lr  = rem / XW;
            int lc  = rem - lr * XW;
            int gr  = r0 + lr - 1;
            int gc  = lc - 1;
            float v = 0.f;
            if ((unsigned)gr < HW && (unsigned)gc < HW) {
                v = xb[(size_t)(ic0 + ic) * (HW * HW) + gr * HW + gc]
                    * __ldg(sb + ic0 + ic);
            }
            xs[ic][lr * XW + lc] = v;
        }

        // ---- load weight tile: 64 oc * (8 ic * 9 taps) = 4608 elements ----
        // global is contiguous over j = ic*9+t for fixed oc (runs of 72 floats)
#pragma unroll
        for (int it = 0; it < (OC_TILE * ICC * KK) / 256; it++) {
            int idx = tid + it * 256;
            int oc  = idx / (ICC * KK);
            int j   = idx - oc * (ICC * KK);
            ws[j * WSTRIDE + oc] =
                w[(size_t)(oc0 + oc) * (CH * KK) + ic0 * KK + j];
        }
        __syncthreads();

        // ---- compute ----
#pragma unroll 1
        for (int ic = 0; ic < ICC; ic++) {
            const float* xrow = &xs[ic][0];
            const float* wrow = &ws[(ic * KK) * WSTRIDE];
#pragma unroll
            for (int kh = 0; kh < 3; kh++) {
#pragma unroll
                for (int kw = 0; kw < 3; kw++) {
                    float wf[8], xf[8];
#pragma unroll
                    for (int o = 0; o < 8; o++)
                        wf[o] = wrow[(kh * 3 + kw) * WSTRIDE + ty * 8 + o];
#pragma unroll
                    for (int r = 0; r < 8; r++)
                        xf[r] = xrow[(r + kh) * XW + tx + kw];
#pragma unroll
                    for (int o = 0; o < 8; o++)
#pragma unroll
                        for (int r = 0; r < 8; r++)
                            acc[o][r] = fmaf(wf[o], xf[r], acc[o][r]);
                }
            }
        }
    }

    // ---- epilogue: scale by G*sigma[b,oc], coalesced stores ----
#pragma unroll
    for (int o = 0; o < 8; o++) {
        int oc  = oc0 + ty * 8 + o;
        float s = g_scale[b * CH + oc];
        float* op = out + (((size_t)b * CH + oc) * HW + r0) * HW + tx;
#pragma unroll
        for (int r = 0; r < 8; r++) op[r * HW] = acc[o][r] * s;
    }
}

// ---------------------------------------------------------------------------
extern "C" void kernel_launch(void* const* d_in, const int* in_sizes, int n_in,
                              void* d_out, int out_size) {
    const float* x     = (const float*)d_in[0];  // [16,512,32,32]
    const float* style = (const float*)d_in[1];  // [16,512]
    const float* w     = (const float*)d_in[2];  // [512,512,3,3]
    float* out = (float*)d_out;                  // [16,512,32,32]

    wsq_kernel<<<(CH * CH + 511) / 512, 512>>>(w);
    scale_kernel<<<BATCH, CH>>>(style);

    dim3 grid(HW / RTILE, CH / OC_TILE, BATCH);  // (4, 8, 16)
    conv_kernel<<<grid, 256>>>(x, style, w, out);
}

// round 13
// speedup vs baseline: 5.1643x; 5.1643x over previous
#include <cuda_runtime.h>
#include <cstdint>
#include <math.h>

#define BATCH 16
#define CH    512
#define HW    32
#define EPSV  1e-8f

// scratch
__device__ float g_wsqT[CH * CH];            // [ic][oc]
__device__ float g_scale[BATCH * CH];        // G * sigma[b][oc]
__device__ float g_wB[9 * CH * CH];          // [k=4608][oc=512], tf32-rounded

__device__ __forceinline__ uint32_t smem_u32(const void* p) {
    uint32_t a;
    asm("{ .reg .u64 t; cvta.to.shared.u64 t, %1; cvt.u32.u64 %0, t; }" : "=r"(a) : "l"(p));
    return a;
}
__device__ __forceinline__ uint32_t f2tf32(float f) {
    uint32_t u; asm("cvt.rna.tf32.f32 %0, %1;" : "=r"(u) : "f"(f)); return u;
}

#define CP_ASYNC16(dst, src) asm volatile("cp.async.cg.shared.global [%0], [%1], 16;" :: "r"(dst), "l"(src) : "memory")
#define CP_COMMIT()          asm volatile("cp.async.commit_group;" ::: "memory")
#define CP_WAIT0()           asm volatile("cp.async.wait_group 0;" ::: "memory")

// D(16x8) += A(16x8) * B(8x8), tf32, row.col
#define MMA_TF32(d, a, bf) \
    asm volatile("mma.sync.aligned.m16n8k8.row.col.f32.tf32.tf32.f32 " \
        "{%0,%1,%2,%3}, {%4,%5,%6,%7}, {%8,%9}, {%0,%1,%2,%3};" \
        : "+f"((d)[0]), "+f"((d)[1]), "+f"((d)[2]), "+f"((d)[3]) \
        : "r"((a)[0]), "r"((a)[1]), "r"((a)[2]), "r"((a)[3]), "r"((bf)[0]), "r"((bf)[1]))

// ===================== prep: wB transpose (tf32) + wsq =====================
// k ordering matches chunk decomposition: k = (ic/8)*72 + (ic%8)*9 + tap
__global__ void prep_kernel(const float* __restrict__ w) {
    int t = blockIdx.x * 256 + threadIdx.x;
    if (t >= CH * CH) return;
    int oc = t >> 9, ic = t & 511;
    int kb = (ic >> 3) * 72 + (ic & 7) * 9;
    const float* p = w + (size_t)t * 9;
    float s = 0.f;
#pragma unroll
    for (int j = 0; j < 9; j++) {
        float v = p[j];
        s += v * v;
        g_wB[(size_t)(kb + j) * CH + oc] = __uint_as_float(f2tf32(v));
    }
    g_wsqT[ic * CH + oc] = s;
}

__global__ void scale_kernel(const float* __restrict__ style) {
    const float GAIN = rsqrtf((float)(CH * 9));
    int b = blockIdx.x, o = threadIdx.x;
    __shared__ float s2[CH];
    float sv = style[b * CH + o];
    s2[o] = sv * sv;
    __syncthreads();
    float acc = 0.f;
#pragma unroll 4
    for (int i = 0; i < CH; i++) acc += s2[i] * g_wsqT[i * CH + o];
    g_scale[b * CH + o] = GAIN * rsqrtf(acc * GAIN * GAIN + EPSV);
}

// ===================== main conv: tf32 mma.sync implicit GEMM =====================
// grid (8 row-bands, 8 oc-groups of 64, 16 batch), 256 threads = 8 warps (4M x 2N).
// Per CTA: D[M=4rows x 32cols][N=64 oc], K=4608 in 64 chunks of 72 (8 ic x 9 taps).
// Warp: M=32 cols of one row (2 m16 tiles) x N=32 (4 n8 tiles), 32 fp32 acc/thread.
// xs tile per ic: 6 rows x 40-float stride (halo at idx 3/36, data at 4..35; 16B-aligned).
#define SM_STY  0
#define SM_SCL  2048
#define SM_XS   2304
#define XS_B    7680            // 8 ic * 6 rows * 160B
#define SM_B    17664
#define B_B     20736           // 72 k-rows * 72-float stride
#define SMEM_TOTAL 59136

__device__ __forceinline__ void load_chunk(
    const float* __restrict__ x, int b, int oc0, int r0,
    int c, int buf, uint32_t smb, int tid)
{
    const int kbase = c * 72, icc0 = c * 8;
    // B chunk: 72 k-rows x 64 floats (16 x 16B each), stride-72 rows (bank-perm on read)
    const uint32_t bdst = smb + SM_B + buf * B_B;
#pragma unroll
    for (int it = 0; it < 5; it++) {
        int i = tid + it * 256;
        if (i < 1152) {
            int r = i >> 4, q = i & 15;
            CP_ASYNC16(bdst + r * 288 + q * 16,
                       g_wB + (size_t)(kbase + r) * CH + oc0 + q * 4);
        }
    }
    // xs chunk: 8 ic x (valid rows of 6) x 8 x 16B vectors
    const uint32_t xdst = smb + SM_XS + buf * XS_B;
#pragma unroll
    for (int it = 0; it < 2; it++) {
        int i = tid + it * 256;
        if (i < 384) {
            int ic = i / 48, rem = i - ic * 48;
            int lr = rem >> 3, q = rem & 7;
            int gr = r0 - 1 + lr;
            if ((unsigned)gr < 32u) {
                CP_ASYNC16(xdst + (ic * 6 + lr) * 160 + 16 + q * 16,
                           x + (((size_t)(b * CH + icc0 + ic)) << 10) + (gr << 5) + q * 4);
            }
        }
    }
}

__global__ void __launch_bounds__(256)
conv_mma(const float* __restrict__ x,
         const float* __restrict__ style,
         float* __restrict__ out) {
    extern __shared__ __align__(16) char sm[];
    float* smf = (float*)sm;
    const uint32_t smb = smem_u32(sm);
    const int tid  = threadIdx.x;
    const int lane = tid & 31;
    const int g    = lane >> 2;       // mma group id 0..7
    const int t4   = lane & 3;        // thread-in-group
    const int warp = tid >> 5;
    const int warpM = warp & 3;       // image row within band
    const int warpN = warp >> 2;      // oc half (0/1) of 64
    const int b   = blockIdx.z;
    const int oc0 = blockIdx.y << 6;
    const int r0  = blockIdx.x << 2;

    // stage styles + scales; zero xs buffers (covers halo cells permanently)
    for (int i = tid; i < CH; i += 256) smf[SM_STY / 4 + i] = style[b * CH + i];
    if (tid < 64) smf[SM_SCL / 4 + tid] = g_scale[b * CH + oc0 + tid];
    for (int i = tid; i < 2 * XS_B / 4; i += 256) smf[SM_XS / 4 + i] = 0.f;
    __syncthreads();

    float acc[2][4][4];
#pragma unroll
    for (int tm = 0; tm < 2; tm++)
#pragma unroll
        for (int tn = 0; tn < 4; tn++)
#pragma unroll
            for (int r = 0; r < 4; r++) acc[tm][tn][r] = 0.f;

    load_chunk(x, b, oc0, r0, 0, 0, smb, tid);
    CP_COMMIT(); CP_WAIT0(); __syncthreads();

    int p = 0;
    for (int c = 0; c < 64; c++) {
        if (c < 63) { load_chunk(x, b, oc0, r0, c + 1, p ^ 1, smb, tid); CP_COMMIT(); }

        const float* xsb = smf + SM_XS / 4 + p * (XS_B / 4);
        const float* bsp = smf + SM_B / 4 + p * (B_B / 4);
        const int sty0 = c * 8;

#pragma unroll
        for (int ks = 0; ks < 9; ks++) {
            // A fragments: rows = spatial cols (M), cols = k
            uint32_t a[2][4];
#pragma unroll
            for (int h = 0; h < 2; h++) {
                int k  = ks * 8 + t4 + h * 4;     // k within chunk (0..71)
                int ic = (k * 57) >> 9;           // k/9
                int tp = k - ic * 9;
                int dh = (tp * 11) >> 5;          // tp/3
                int dw = tp - dh * 3;
                float sv = smf[SM_STY / 4 + sty0 + ic];
                int base = ic * 240 + (warpM + dh) * 40 + dw + 3;
#pragma unroll
                for (int tm = 0; tm < 2; tm++) {
#pragma unroll
                    for (int mh = 0; mh < 2; mh++) {
                        int mc = tm * 16 + mh * 8 + g;
                        a[tm][h * 2 + mh] = f2tf32(xsb[base + mc] * sv);
                    }
                }
            }
            // B fragments: b0=[k=t4][n], b1=[k=t4+4][n]
            uint32_t bf[4][2];
            const int krow = (ks * 8 + t4) * 72;
#pragma unroll
            for (int tn = 0; tn < 4; tn++) {
                int n = warpN * 32 + tn * 8 + g;
                bf[tn][0] = __float_as_uint(bsp[krow + n]);
                bf[tn][1] = __float_as_uint(bsp[krow + 288 + n]);
            }
#pragma unroll
            for (int tm = 0; tm < 2; tm++)
#pragma unroll
                for (int tn = 0; tn < 4; tn++)
                    MMA_TF32(acc[tm][tn], a[tm], bf[tn]);
        }

        if (c < 63) { CP_WAIT0(); __syncthreads(); p ^= 1; }
    }

    // epilogue: demod scale + store
    const int row = r0 + warpM;
#pragma unroll
    for (int tm = 0; tm < 2; tm++) {
#pragma unroll
        for (int tn = 0; tn < 4; tn++) {
#pragma unroll
            for (int r = 0; r < 4; r++) {
                int mc  = tm * 16 + ((r & 2) ? 8 : 0) + g;
                int ocl = warpN * 32 + tn * 8 + 2 * t4 + (r & 1);
                out[(((size_t)(b * CH + oc0 + ocl)) << 10) + (row << 5) + mc] =
                    acc[tm][tn][r] * smf[SM_SCL / 4 + ocl];
            }
        }
    }
}

// ===================== launch =====================
extern "C" void kernel_launch(void* const* d_in, const int* in_sizes, int n_in,
                              void* d_out, int out_size) {
    const float* x     = (const float*)d_in[0];
    const float* style = (const float*)d_in[1];
    const float* w     = (const float*)d_in[2];
    float* out = (float*)d_out;

    cudaFuncSetAttribute(conv_mma, cudaFuncAttributeMaxDynamicSharedMemorySize, SMEM_TOTAL);

    prep_kernel<<<(CH * CH + 255) / 256, 256>>>(w);
    scale_kernel<<<BATCH, CH>>>(style);
    dim3 grid(8, 8, BATCH);
    conv_mma<<<grid, 256, SMEM_TOTAL>>>(x, style, out);
}